// round 1
// baseline (speedup 1.0000x reference)
#include <cuda_runtime.h>
#include <math.h>

#define N_NODES 50000
#define N_EDGES 1600000
#define E_TOT   (N_EDGES + N_NODES)
#define N_PAIRS 2000000
#define N_GRAPHS 50
#define FDIM 128

// ---------------- device scratch (static, no runtime alloc) ----------------
__device__ float g_h384[N_NODES * 384];
__device__ float g_xl[N_NODES * FDIM];
__device__ float g_xr[N_NODES * FDIM];
__device__ float g_h2[N_NODES * FDIM];
__device__ float g_hb[N_NODES * FDIM];
__device__ int   g_deg[N_NODES];
__device__ int   g_off[N_NODES + 1];
__device__ int   g_cur[N_NODES];
__device__ int   g_csr_src[E_TOT];
__device__ float g_gsum[N_GRAPHS];
__device__ float g_gss[N_GRAPHS];
__device__ float g_gcnt[N_GRAPHS];

__device__ __forceinline__ float lrelu(float x) { return x > 0.f ? x : 0.2f * x; }

// ---------------- time embedding: h384 = concat(x, swish(feats @ tW + tb)) --
__global__ void embed_kernel(const float* __restrict__ x, const float* __restrict__ t,
                             const float* __restrict__ tW, const float* __restrict__ tb) {
    int node = blockIdx.x;
    int tid = threadIdx.x;  // 256
    float tv = t[node];
    float s, c;
    __sincosf(tv * 1.57079632679f, &s, &c);
    if (tid < 128)
        g_h384[(size_t)node * 384 + tid] = x[(size_t)node * 128 + tid];
    float te = s * tW[tid] + c * tW[256 + tid] + tv * tW[512 + tid] + tb[tid];
    float sw = te / (1.f + __expf(-te));
    g_h384[(size_t)node * 384 + 128 + tid] = sw;
}

// ---------------- CSR build ------------------------------------------------
__global__ void zero_deg_kernel() {
    for (int i = blockIdx.x * blockDim.x + threadIdx.x; i < N_NODES; i += gridDim.x * blockDim.x)
        g_deg[i] = 0;
}

__global__ void count_kernel(const int* __restrict__ ei) {
    for (int e = blockIdx.x * blockDim.x + threadIdx.x; e < E_TOT; e += gridDim.x * blockDim.x) {
        int d = (e < N_EDGES) ? ei[N_EDGES + e] : (e - N_EDGES);
        atomicAdd(&g_deg[d], 1);
    }
}

__global__ void scan_kernel() {
    __shared__ int s[1024];
    int tid = threadIdx.x;
    const int CH = (N_NODES + 1023) / 1024;  // 49
    int start = tid * CH;
    int end = start + CH; if (end > N_NODES) end = N_NODES;
    int sum = 0;
    for (int i = start; i < end && i < N_NODES; i++) sum += g_deg[i];
    if (start >= N_NODES) sum = 0;
    s[tid] = sum;
    __syncthreads();
    for (int off = 1; off < 1024; off <<= 1) {
        int v = 0;
        if (tid >= off) v = s[tid - off];
        __syncthreads();
        if (tid >= off) s[tid] += v;
        __syncthreads();
    }
    int prefix = (tid == 0) ? 0 : s[tid - 1];
    for (int i = start; i < end && i < N_NODES; i++) {
        g_off[i] = prefix;
        g_cur[i] = prefix;
        prefix += g_deg[i];
    }
    if (tid == 1023) g_off[N_NODES] = s[1023];
}

__global__ void scatter_kernel(const int* __restrict__ ei) {
    for (int e = blockIdx.x * blockDim.x + threadIdx.x; e < E_TOT; e += gridDim.x * blockDim.x) {
        int srcv, d;
        if (e < N_EDGES) { srcv = ei[e]; d = ei[N_EDGES + e]; }
        else { srcv = e - N_EDGES; d = srcv; }
        int pos = atomicAdd(&g_cur[d], 1);
        g_csr_src[pos] = srcv;
    }
}

// ---------------- GEMM: y[N,128] = h[N,K] @ W[K,128] + b --------------------
// block = 256 threads, 32 nodes/block, K tiled by 64.
__global__ void gemm_kernel(const float* __restrict__ h, int K,
                            const float* __restrict__ W, const float* __restrict__ b,
                            float* __restrict__ y) {
    __shared__ float Ws[64 * 128];
    __shared__ float hs[32 * 64];
    int t = threadIdx.x;
    int cg = t & 31;     // column group: 4 cols
    int ng = t >> 5;     // node group: 4 nodes
    int nb = blockIdx.x * 32;

    float4 acc[4];
#pragma unroll
    for (int j = 0; j < 4; j++) acc[j] = make_float4(0.f, 0.f, 0.f, 0.f);

    for (int kt = 0; kt < K; kt += 64) {
        // load W tile: 64 rows x 128 cols = 2048 float4
        const float4* Wg = (const float4*)(W + (size_t)kt * 128);
        float4* Ws4 = (float4*)Ws;
        for (int i = t; i < 2048; i += 256) Ws4[i] = Wg[i];
        // load h tile: 32 nodes x 64 = 512 float4
        float4* hs4 = (float4*)hs;
        for (int i = t; i < 512; i += 256) {
            int node = i >> 4, c4 = i & 15;
            int gn = nb + node;
            float4 v = make_float4(0.f, 0.f, 0.f, 0.f);
            if (gn < N_NODES)
                v = *(const float4*)(h + (size_t)gn * K + kt + c4 * 4);
            hs4[i] = v;
        }
        __syncthreads();
#pragma unroll 8
        for (int k = 0; k < 64; k++) {
            float4 w = ((float4*)Ws)[k * 32 + cg];
#pragma unroll
            for (int j = 0; j < 4; j++) {
                float hv = hs[(ng * 4 + j) * 64 + k];
                acc[j].x += hv * w.x;
                acc[j].y += hv * w.y;
                acc[j].z += hv * w.z;
                acc[j].w += hv * w.w;
            }
        }
        __syncthreads();
    }
    float4 bb = ((const float4*)b)[cg];
#pragma unroll
    for (int j = 0; j < 4; j++) {
        int node = nb + ng * 4 + j;
        if (node < N_NODES) {
            float4 o = acc[j];
            o.x += bb.x; o.y += bb.y; o.z += bb.z; o.w += bb.w;
            *(float4*)(y + (size_t)node * 128 + cg * 4) = o;
        }
    }
}

// ---------------- GATv2 aggregation: warp per node, online softmax ----------
__global__ void agg_kernel(const float* __restrict__ xl, const float* __restrict__ xr,
                           const float* __restrict__ att, const float* __restrict__ bias,
                           float* __restrict__ out) {
    int wid = (blockIdx.x * blockDim.x + threadIdx.x) >> 5;
    int lane = threadIdx.x & 31;
    if (wid >= N_NODES) return;
    int v = wid;
    int head = lane >> 3;
    float4 xr4 = *(const float4*)(xr + (size_t)v * 128 + lane * 4);
    float4 at4 = *(const float4*)(att + head * 32 + (lane & 7) * 4);
    float4 acc = make_float4(0.f, 0.f, 0.f, 0.f);
    float mx = -INFINITY, denom = 0.f;
    int beg = g_off[v], end = g_off[v + 1];
    for (int p = beg; p < end; p++) {
        int s = g_csr_src[p];
        float4 a4 = *(const float4*)(xl + (size_t)s * 128 + lane * 4);
        float mx_ = lrelu(a4.x + xr4.x);
        float my_ = lrelu(a4.y + xr4.y);
        float mz_ = lrelu(a4.z + xr4.z);
        float mw_ = lrelu(a4.w + xr4.w);
        float pt = mx_ * at4.x + my_ * at4.y + mz_ * at4.z + mw_ * at4.w;
        pt += __shfl_xor_sync(0xffffffffu, pt, 1);
        pt += __shfl_xor_sync(0xffffffffu, pt, 2);
        pt += __shfl_xor_sync(0xffffffffu, pt, 4);
        float nm = fmaxf(mx, pt);
        float scale = __expf(mx - nm);   // first iter: exp(-inf)=0
        float w = __expf(pt - nm);
        denom = denom * scale + w;
        acc.x = acc.x * scale + w * a4.x;
        acc.y = acc.y * scale + w * a4.y;
        acc.z = acc.z * scale + w * a4.z;
        acc.w = acc.w * scale + w * a4.w;
        mx = nm;
    }
    float inv = 1.f / (denom + 1e-16f);
    float4 b4 = *(const float4*)(bias + lane * 4);
    float4 o;
    o.x = acc.x * inv + b4.x;
    o.y = acc.y * inv + b4.y;
    o.z = acc.z * inv + b4.z;
    o.w = acc.w * inv + b4.w;
    *(float4*)(out + (size_t)v * 128 + lane * 4) = o;
}

// ---------------- graph layernorm -------------------------------------------
__global__ void zero_stats_kernel() {
    int i = threadIdx.x;
    if (i < N_GRAPHS) { g_gsum[i] = 0.f; g_gss[i] = 0.f; g_gcnt[i] = 0.f; }
}

__global__ void ln_stats_kernel(const float* __restrict__ h, const int* __restrict__ batch) {
    int wid = (blockIdx.x * blockDim.x + threadIdx.x) >> 5;
    int lane = threadIdx.x & 31;
    if (wid >= N_NODES) return;
    float4 hv = *(const float4*)(h + (size_t)wid * 128 + lane * 4);
    float s = hv.x + hv.y + hv.z + hv.w;
    float q = hv.x * hv.x + hv.y * hv.y + hv.z * hv.z + hv.w * hv.w;
#pragma unroll
    for (int o = 16; o > 0; o >>= 1) {
        s += __shfl_xor_sync(0xffffffffu, s, o);
        q += __shfl_xor_sync(0xffffffffu, q, o);
    }
    if (lane == 0) {
        int g = batch[wid];
        atomicAdd(&g_gsum[g], s);
        atomicAdd(&g_gss[g], q);
        atomicAdd(&g_gcnt[g], 1.0f);
    }
}

__global__ void ln_apply_kernel(const float* __restrict__ h, const int* __restrict__ batch,
                                const float* __restrict__ w, const float* __restrict__ b,
                                float* __restrict__ out) {
    int idx = blockIdx.x * blockDim.x + threadIdx.x;
    if (idx >= N_NODES * 32) return;
    int node = idx >> 5;
    int c4 = idx & 31;
    int g = batch[node];
    float cnt = fmaxf(g_gcnt[g] * 128.f, 1.f);
    float mean = g_gsum[g] / cnt;
    float var = fmaxf(g_gss[g] / cnt - mean * mean, 0.f);
    float inv = rsqrtf(var + 1e-5f);
    float4 hv = *(const float4*)(h + (size_t)node * 128 + c4 * 4);
    float4 w4 = ((const float4*)w)[c4];
    float4 b4 = ((const float4*)b)[c4];
    float4 o;
    o.x = (hv.x - mean) * inv * w4.x + b4.x;
    o.y = (hv.y - mean) * inv * w4.y + b4.y;
    o.z = (hv.z - mean) * inv * w4.z + b4.z;
    o.w = (hv.w - mean) * inv * w4.w + b4.w;
    *(float4*)(out + (size_t)node * 128 + c4 * 4) = o;
}

// ---------------- pair scoring ----------------------------------------------
__global__ void pair_kernel(const float* __restrict__ h, const int* __restrict__ pidx,
                            const float* __restrict__ linkW, const float* __restrict__ linkb,
                            float* __restrict__ out) {
    int wid = (blockIdx.x * blockDim.x + threadIdx.x) >> 5;
    int lane = threadIdx.x & 31;
    if (wid >= N_PAIRS) return;
    int a = pidx[wid];
    int bnode = pidx[N_PAIRS + wid];
    float4 ha = *(const float4*)(h + (size_t)a * 128 + lane * 4);
    float4 hb = *(const float4*)(h + (size_t)bnode * 128 + lane * 4);
    float4 lw = ((const float4*)linkW)[lane];
    float d = ha.x * hb.x * lw.x + ha.y * hb.y * lw.y + ha.z * hb.z * lw.z + ha.w * hb.w * lw.w;
#pragma unroll
    for (int o = 16; o > 0; o >>= 1) d += __shfl_xor_sync(0xffffffffu, d, o);
    if (lane == 0) {
        float z = d + linkb[0];
        out[wid] = 1.f / (1.f + __expf(-z));
    }
}

// ---------------- host orchestration ----------------------------------------
extern "C" void kernel_launch(void* const* d_in, const int* in_sizes, int n_in,
                              void* d_out, int out_size) {
    const float* x     = (const float*)d_in[0];
    const float* t     = (const float*)d_in[1];
    const int*   ei    = (const int*)d_in[2];
    const int*   pidx  = (const int*)d_in[3];
    const int*   batch = (const int*)d_in[4];
    const float* tW    = (const float*)d_in[5];
    const float* tb    = (const float*)d_in[6];
    const float* W0l   = (const float*)d_in[7];
    const float* b0l   = (const float*)d_in[8];
    const float* W0r   = (const float*)d_in[9];
    const float* b0r   = (const float*)d_in[10];
    const float* att0  = (const float*)d_in[11];
    const float* bias0 = (const float*)d_in[12];
    const float* Wl    = (const float*)d_in[13];
    const float* bl    = (const float*)d_in[14];
    const float* Wr    = (const float*)d_in[15];
    const float* br    = (const float*)d_in[16];
    const float* att   = (const float*)d_in[17];
    const float* bias  = (const float*)d_in[18];
    const float* lnw   = (const float*)d_in[19];
    const float* lnb   = (const float*)d_in[20];
    const float* linkW = (const float*)d_in[21];
    const float* linkb = (const float*)d_in[22];
    float* out = (float*)d_out;

    // resolve scratch buffer device pointers via kernels (symbols used directly)
    float *hb, *h2, *xl, *xr;
    // (we only use device symbols inside kernels; host just orders launches)

    // 1. time embedding -> g_h384
    embed_kernel<<<N_NODES, 256>>>(x, t, tW, tb);

    // 2. CSR build (dst-major) -> g_off / g_csr_src
    zero_deg_kernel<<<256, 256>>>();
    count_kernel<<<(E_TOT + 255) / 256, 256>>>(ei);
    scan_kernel<<<1, 1024>>>();
    scatter_kernel<<<(E_TOT + 255) / 256, 256>>>(ei);

    const int GEMM_BLKS = (N_NODES + 31) / 32;
    const int WARP_BLKS = (N_NODES + 7) / 8;          // warp-per-node kernels
    const int APPLY_BLKS = (N_NODES * 32 + 255) / 256;

    // --- layer 0 (K = 384) ---
    {
        // device symbol addresses are taken inside kernels; here we pass
        // through extern helpers by launching with symbol-bound kernels.
        // Use explicit wrappers via pointers to __device__ arrays:
        // CUDA allows taking their address in device code only, so the
        // kernels reference them directly; GEMM I/O uses parameters, so
        // fetch raw pointers with cudaGetSymbolAddress (host API, capture-safe).
        static float* p_h384 = nullptr;
        static float* p_xl = nullptr;
        static float* p_xr = nullptr;
        static float* p_h2 = nullptr;
        static float* p_hb = nullptr;
        if (!p_h384) {
            cudaGetSymbolAddress((void**)&p_h384, g_h384);
            cudaGetSymbolAddress((void**)&p_xl, g_xl);
            cudaGetSymbolAddress((void**)&p_xr, g_xr);
            cudaGetSymbolAddress((void**)&p_h2, g_h2);
            cudaGetSymbolAddress((void**)&p_hb, g_hb);
        }

        gemm_kernel<<<GEMM_BLKS, 256>>>(p_h384, 384, W0l, b0l, p_xl);
        gemm_kernel<<<GEMM_BLKS, 256>>>(p_h384, 384, W0r, b0r, p_xr);
        agg_kernel<<<WARP_BLKS, 256>>>(p_xl, p_xr, att0, bias0, p_h2);
        zero_stats_kernel<<<1, 64>>>();
        ln_stats_kernel<<<WARP_BLKS, 256>>>(p_h2, batch);
        ln_apply_kernel<<<APPLY_BLKS, 256>>>(p_h2, batch, lnw, lnb, p_hb);

        // --- layers 1..3 (K = 128) ---
        for (int i = 0; i < 3; i++) {
            const float* Wli = Wl + (size_t)i * 128 * 128;
            const float* bli = bl + (size_t)i * 128;
            const float* Wri = Wr + (size_t)i * 128 * 128;
            const float* bri = br + (size_t)i * 128;
            const float* ai  = att + (size_t)i * 128;
            const float* bi  = bias + (size_t)i * 128;
            gemm_kernel<<<GEMM_BLKS, 256>>>(p_hb, 128, Wli, bli, p_xl);
            gemm_kernel<<<GEMM_BLKS, 256>>>(p_hb, 128, Wri, bri, p_xr);
            agg_kernel<<<WARP_BLKS, 256>>>(p_xl, p_xr, ai, bi, p_h2);
            zero_stats_kernel<<<1, 64>>>();
            ln_stats_kernel<<<WARP_BLKS, 256>>>(p_h2, batch);
            ln_apply_kernel<<<APPLY_BLKS, 256>>>(p_h2, batch,
                                                 lnw + (size_t)(i + 1) * 128,
                                                 lnb + (size_t)(i + 1) * 128, p_hb);
        }

        // 3. pair scoring
        pair_kernel<<<(N_PAIRS * 32 + 255) / 256, 256>>>(p_hb, pidx, linkW, linkb, out);
    }
    (void)hb; (void)h2; (void)xl; (void)xr;
    (void)in_sizes; (void)n_in; (void)out_size;
}